// round 1
// baseline (speedup 1.0000x reference)
#include <cuda_runtime.h>
#include <math.h>

#define H 1024
#define V 50257
#define S 4096
#define NLSE 128

// ---------------- scratch (device globals; no allocation allowed) ----------
__device__ float g_hnew[H];
__device__ float g_scores[S];
__device__ float g_attn[S];
__device__ float g_context[H];
__device__ float g_xc[2 * H];
__device__ float g_logits[V];
__device__ float g_lse_m[NLSE];
__device__ float g_lse_s[NLSE];

// ---------------- helpers --------------------------------------------------
__device__ __forceinline__ float dot4(float4 a, float4 b) {
    return a.x * b.x + a.y * b.y + a.z * b.z + a.w * b.w;
}
__device__ __forceinline__ float warp_sum(float v) {
    #pragma unroll
    for (int o = 16; o > 0; o >>= 1) v += __shfl_xor_sync(0xffffffffu, v, o);
    return v;
}
__device__ __forceinline__ float warp_max(float v) {
    #pragma unroll
    for (int o = 16; o > 0; o >>= 1) v = fmaxf(v, __shfl_xor_sync(0xffffffffu, v, o));
    return v;
}

// ---------------- K1: fused GRU cell. 1024 blocks x 256 threads ------------
// block j computes rows {j, j+H, j+2H} of w_ih@x and w_hh@h, then h_new[j].
__global__ void gru_kernel(const int* __restrict__ word,
                           const float* __restrict__ last_ctx,
                           const float* __restrict__ last_h,
                           const float* __restrict__ emb,
                           const float* __restrict__ w_ih,
                           const float* __restrict__ w_hh,
                           const float* __restrict__ b_ih,
                           const float* __restrict__ b_hh,
                           float* __restrict__ d_out) {
    const int j = blockIdx.x;
    const int tid = threadIdx.x;

    const float4* e4 = (const float4*)(emb + (size_t)word[0] * H);
    const float4* c4 = (const float4*)last_ctx;
    const float4* h4 = (const float4*)last_h;
    const float4* wr = (const float4*)(w_ih + (size_t)(j)        * 2 * H);
    const float4* wz = (const float4*)(w_ih + (size_t)(j + H)    * 2 * H);
    const float4* wn = (const float4*)(w_ih + (size_t)(j + 2*H)  * 2 * H);
    const float4* ur = (const float4*)(w_hh + (size_t)(j)        * H);
    const float4* uz = (const float4*)(w_hh + (size_t)(j + H)    * H);
    const float4* un = (const float4*)(w_hh + (size_t)(j + 2*H)  * H);

    float ar = 0.f, az = 0.f, an = 0.f, br = 0.f, bz = 0.f, bn = 0.f;

    // x = [emb_row, last_context]: 512 float4s
    #pragma unroll
    for (int k = 0; k < 2; k++) {
        int c = tid + 256 * k;
        float4 x = (c < 256) ? e4[c] : c4[c - 256];
        ar += dot4(wr[c], x);
        az += dot4(wz[c], x);
        an += dot4(wn[c], x);
    }
    // h: 256 float4s
    {
        int c = tid;
        float4 hh = h4[c];
        br += dot4(ur[c], hh);
        bz += dot4(uz[c], hh);
        bn += dot4(un[c], hh);
    }

    ar = warp_sum(ar); az = warp_sum(az); an = warp_sum(an);
    br = warp_sum(br); bz = warp_sum(bz); bn = warp_sum(bn);

    __shared__ float red[6][8];
    int w = tid >> 5, l = tid & 31;
    if (l == 0) {
        red[0][w] = ar; red[1][w] = az; red[2][w] = an;
        red[3][w] = br; red[4][w] = bz; red[5][w] = bn;
    }
    __syncthreads();
    if (tid == 0) {
        float s[6];
        #pragma unroll
        for (int k = 0; k < 6; k++) {
            float acc = red[k][0];
            #pragma unroll
            for (int q = 1; q < 8; q++) acc += red[k][q];
            s[k] = acc;
        }
        float ir = s[0] + b_ih[j];
        float iz = s[1] + b_ih[j + H];
        float in_ = s[2] + b_ih[j + 2 * H];
        float hr = s[3] + b_hh[j];
        float hz = s[4] + b_hh[j + H];
        float hn = s[5] + b_hh[j + 2 * H];
        float r = 1.f / (1.f + expf(-(ir + hr)));
        float z = 1.f / (1.f + expf(-(iz + hz)));
        float n = tanhf(in_ + r * hn);
        float hv = last_h[j];
        float hnew = (1.f - z) * n + z * hv;
        g_hnew[j] = hnew;
        d_out[V + H + j] = hnew;   // h_new slot
    }
}

// ---------------- K2: scores[s] = enc[s] . h_new. 4096 blocks x 128 -------
__global__ void scores_kernel(const float* __restrict__ enc) {
    const int s = blockIdx.x;
    const int tid = threadIdx.x;
    const float4* e4 = (const float4*)(enc + (size_t)s * H);
    const float4* h4 = (const float4*)g_hnew;
    float acc = 0.f;
    #pragma unroll
    for (int k = 0; k < 2; k++) {
        int c = tid + 128 * k;
        acc += dot4(e4[c], h4[c]);
    }
    acc = warp_sum(acc);
    __shared__ float red[4];
    if ((tid & 31) == 0) red[tid >> 5] = acc;
    __syncthreads();
    if (tid == 0) g_scores[s] = red[0] + red[1] + red[2] + red[3];
}

// ---------------- K3: softmax over 4096. 1 block x 1024; also zero ctx ----
__global__ void softmax_kernel(float* __restrict__ d_out) {
    const int tid = threadIdx.x;
    float v0 = g_scores[tid];
    float v1 = g_scores[tid + 1024];
    float v2 = g_scores[tid + 2048];
    float v3 = g_scores[tid + 3072];
    float m = fmaxf(fmaxf(v0, v1), fmaxf(v2, v3));

    __shared__ float sm[32];
    m = warp_max(m);
    if ((tid & 31) == 0) sm[tid >> 5] = m;
    __syncthreads();
    if (tid < 32) { float t = sm[tid]; t = warp_max(t); if (tid == 0) sm[0] = t; }
    __syncthreads();
    m = sm[0];

    float e0 = expf(v0 - m), e1 = expf(v1 - m), e2 = expf(v2 - m), e3 = expf(v3 - m);
    float ssum = e0 + e1 + e2 + e3;
    __shared__ float ss[32];
    ssum = warp_sum(ssum);
    if ((tid & 31) == 0) ss[tid >> 5] = ssum;
    __syncthreads();
    if (tid < 32) { float t = ss[tid]; t = warp_sum(t); if (tid == 0) ss[0] = t; }
    __syncthreads();
    float inv = 1.f / ss[0];

    float a0 = e0 * inv, a1 = e1 * inv, a2 = e2 * inv, a3 = e3 * inv;
    g_attn[tid]        = a0;  d_out[V + 2 * H + tid]        = a0;
    g_attn[tid + 1024] = a1;  d_out[V + 2 * H + tid + 1024] = a1;
    g_attn[tid + 2048] = a2;  d_out[V + 2 * H + tid + 2048] = a2;
    g_attn[tid + 3072] = a3;  d_out[V + 2 * H + tid + 3072] = a3;

    g_context[tid] = 0.f;   // zero for K4's atomic accumulation
}

// ---------------- K4: context = attn @ enc. grid (2, 64) x 128 ------------
__global__ void context_kernel(const float* __restrict__ enc) {
    const int d4 = blockIdx.x * 128 + threadIdx.x;   // float4 index in [0,256)
    const int s0 = blockIdx.y * 64;
    const float4* e4 = (const float4*)enc;
    float4 acc = make_float4(0.f, 0.f, 0.f, 0.f);
    #pragma unroll 4
    for (int s = s0; s < s0 + 64; s++) {
        float a = g_attn[s];
        float4 e = e4[(size_t)s * 256 + d4];
        acc.x += a * e.x; acc.y += a * e.y; acc.z += a * e.z; acc.w += a * e.w;
    }
    atomicAdd(&g_context[d4 * 4 + 0], acc.x);
    atomicAdd(&g_context[d4 * 4 + 1], acc.y);
    atomicAdd(&g_context[d4 * 4 + 2], acc.z);
    atomicAdd(&g_context[d4 * 4 + 3], acc.w);
}

// ---------------- K5: build xc = [h_new, context], write context out ------
__global__ void xc_kernel(float* __restrict__ d_out) {
    const int i = blockIdx.x * 1024 + threadIdx.x;   // grid 2
    if (i < 1024) {
        g_xc[i] = g_hnew[i];
    } else {
        float c = g_context[i - 1024];
        g_xc[i] = c;
        d_out[V + (i - 1024)] = c;   // context slot
    }
}

// ---------------- K6: logits = out_w @ xc + out_b. 50257 blocks x 128 -----
__global__ void logits_kernel(const float* __restrict__ out_w,
                              const float* __restrict__ out_b) {
    const int v = blockIdx.x;
    const int tid = threadIdx.x;
    const float4* w4 = (const float4*)(out_w + (size_t)v * 2 * H);
    const float4* x4 = (const float4*)g_xc;
    float acc = 0.f;
    #pragma unroll
    for (int k = 0; k < 4; k++) {
        int c = tid + 128 * k;
        acc += dot4(w4[c], x4[c]);
    }
    acc = warp_sum(acc);
    __shared__ float red[4];
    if ((tid & 31) == 0) red[tid >> 5] = acc;
    __syncthreads();
    if (tid == 0) g_logits[v] = red[0] + red[1] + red[2] + red[3] + out_b[v];
}

// ---------------- K7a: blockwise online logsumexp partials. 128 x 256 -----
__global__ void lse_partial_kernel() {
    const int b = blockIdx.x;
    const int tid = threadIdx.x;
    const int chunk = (V + NLSE - 1) / NLSE;            // 393
    const int lo = b * chunk;
    const int hi = min(lo + chunk, V);

    float m = -INFINITY, s = 0.f;
    for (int i = lo + tid; i < hi; i += 256) {
        float x = g_logits[i];
        float nm = fmaxf(m, x);
        s = s * expf(m - nm) + expf(x - nm);
        m = nm;
    }
    // warp merge of (m, s) pairs
    #pragma unroll
    for (int o = 16; o > 0; o >>= 1) {
        float om = __shfl_xor_sync(0xffffffffu, m, o);
        float os = __shfl_xor_sync(0xffffffffu, s, o);
        float nm = fmaxf(m, om);
        s = s * expf(m - nm) + os * expf(om - nm);
        m = nm;
    }
    __shared__ float shm[8], shs[8];
    if ((tid & 31) == 0) { shm[tid >> 5] = m; shs[tid >> 5] = s; }
    __syncthreads();
    if (tid == 0) {
        float mm = shm[0], sacc = shs[0];
        #pragma unroll
        for (int k = 1; k < 8; k++) {
            float om = shm[k], os = shs[k];
            float nm = fmaxf(mm, om);
            sacc = sacc * expf(mm - nm) + os * expf(om - nm);
            mm = nm;
        }
        g_lse_m[b] = mm;
        g_lse_s[b] = sacc;
    }
}

// ---------------- K7b: final write. ceil(V/256) blocks x 256 --------------
__global__ void write_output_kernel(float* __restrict__ d_out) {
    // redundantly merge the 128 partials per block (all L2-hot, trivial)
    float m = -INFINITY, s = 0.f;
    #pragma unroll 1
    for (int k = 0; k < NLSE; k++) {
        float om = g_lse_m[k], os = g_lse_s[k];
        float nm = fmaxf(m, om);
        s = s * expf(m - nm) + os * expf(om - nm);
        m = nm;
    }
    float logz = m + logf(s);
    int v = blockIdx.x * 256 + threadIdx.x;
    if (v < V) d_out[v] = g_logits[v] - logz;
}

// ---------------- launch ---------------------------------------------------
extern "C" void kernel_launch(void* const* d_in, const int* in_sizes, int n_in,
                              void* d_out, int out_size) {
    const int*   word     = (const int*)  d_in[0];
    const float* last_ctx = (const float*)d_in[1];
    const float* last_h   = (const float*)d_in[2];
    const float* enc      = (const float*)d_in[3];
    const float* emb      = (const float*)d_in[4];
    const float* w_ih     = (const float*)d_in[5];
    const float* w_hh     = (const float*)d_in[6];
    const float* b_ih     = (const float*)d_in[7];
    const float* b_hh     = (const float*)d_in[8];
    const float* out_w    = (const float*)d_in[9];
    const float* out_b    = (const float*)d_in[10];
    float* out = (float*)d_out;

    gru_kernel<<<H, 256>>>(word, last_ctx, last_h, emb, w_ih, w_hh, b_ih, b_hh, out);
    scores_kernel<<<S, 128>>>(enc);
    softmax_kernel<<<1, 1024>>>(out);
    {
        dim3 g(2, 64);
        context_kernel<<<g, 128>>>(enc);
    }
    xc_kernel<<<2, 1024>>>(out);
    logits_kernel<<<V, 128>>>(out_w, out_b);
    lse_partial_kernel<<<NLSE, 256>>>();
    write_output_kernel<<<(V + 255) / 256, 256>>>(out);
}